// round 10
// baseline (speedup 1.0000x reference)
#include <cuda_runtime.h>
#include <cstdint>

#define B_  4
#define S_  2048
#define D_  1024
#define H_  16
#define DK_ 64
#define M_  (B_*S_)   // 8192 rows

// ---------------- scratch (device globals: no allocation allowed) ----------
__device__ float g_q  [(size_t)M_ * D_];
__device__ float g_k  [(size_t)M_ * D_];
__device__ float g_v  [(size_t)M_ * D_];
__device__ float g_att[(size_t)M_ * D_];
__device__ float g_wt [4][(size_t)D_ * D_];   // W transposed + tf32-rounded

// ---------------- f32x2 packed helpers (full-rate fp32 on sm_103a) --------
typedef unsigned long long u64;

__device__ __forceinline__ u64 f32x2_dup(float a) {
    u64 r; asm("mov.b64 %0, {%1, %1};" : "=l"(r) : "f"(a)); return r;
}
__device__ __forceinline__ void f32x2_unpack(u64 v, float& lo, float& hi) {
    asm("mov.b64 {%0, %1}, %2;" : "=f"(lo), "=f"(hi) : "l"(v));
}
__device__ __forceinline__ void f32x2_fma(u64& d, u64 a, u64 b) {
    asm("fma.rn.f32x2 %0, %1, %2, %3;" : "=l"(d) : "l"(a), "l"(b), "l"(d));
}
__device__ __forceinline__ void f32x2_mul(u64& d, u64 a, u64 b) {
    asm("mul.rn.f32x2 %0, %1, %2;" : "=l"(d) : "l"(a), "l"(b));
}

__device__ __forceinline__ uint32_t cvt_tf32(float f) {
    uint32_t u; asm("cvt.rna.tf32.f32 %0, %1;" : "=r"(u) : "f"(f)); return u;
}

// mma.sync m16n8k8 tf32 (legacy tensor-core path; valid on compute_103)
__device__ __forceinline__ void mma_tf32(float* c, const uint32_t* a, const uint32_t* b) {
    asm volatile(
        "mma.sync.aligned.m16n8k8.row.col.f32.tf32.tf32.f32 "
        "{%0,%1,%2,%3}, {%4,%5,%6,%7}, {%8,%9}, {%0,%1,%2,%3};"
        : "+f"(c[0]), "+f"(c[1]), "+f"(c[2]), "+f"(c[3])
        : "r"(a[0]), "r"(a[1]), "r"(a[2]), "r"(a[3]), "r"(b[0]), "r"(b[1]));
}

// ---------------- W transpose + tf32 round: Wt[n][k] = tf32(W[k][n]) -------
__global__ void transpose_tf32_kernel(const float* __restrict__ W,
                                      float* __restrict__ Wt)
{
    __shared__ float t[32][33];
    const int tx = threadIdx.x, ty = threadIdx.y;       // 32 x 8
    const int nb = blockIdx.x * 32, kb = blockIdx.y * 32;
    #pragma unroll
    for (int i = 0; i < 32; i += 8)
        t[ty + i][tx] = W[(size_t)(kb + ty + i) * D_ + nb + tx];
    __syncthreads();
    #pragma unroll
    for (int i = 0; i < 32; i += 8) {
        uint32_t v = cvt_tf32(t[tx][ty + i]);
        Wt[(size_t)(nb + ty + i) * D_ + kb + tx] = __uint_as_float(v);
    }
}

// ---------------- mma.sync tf32 GEMM: C[M,1024] = A @ W^T(Kmajor) + bias ---
// CTA 128x128, BK=32. 8 warps as 2(m) x 4(n); warp tile 64x32 = 4x4 m16n8k8.
// smem holds tiles in FRAGMENT order: A [mtile][kstep][lane][4], B
// [ntile][kstep][lane][2] -> fragment fetch is 1 conflict-free LDS.128/LDS.64.
__global__ __launch_bounds__(256, 2)
void gemm_mma_kernel(const float* __restrict__ A, const float* __restrict__ Wt,
                     const float* __restrict__ bias, float* __restrict__ C)
{
    __shared__ uint32_t As[8 * 4 * 32 * 4];   // 16 KB
    __shared__ uint32_t Bs[16 * 4 * 32 * 2];  // 16 KB

    const int tid  = threadIdx.x;
    const int wid  = tid >> 5, lane = tid & 31;
    const int m0 = blockIdx.y * 128, n0 = blockIdx.x * 128;
    const int wm = wid >> 2, wn = wid & 3;    // warp grid 2 x 4

    float acc[4][4][4];
    #pragma unroll
    for (int i = 0; i < 4; i++)
        #pragma unroll
        for (int j = 0; j < 4; j++)
            #pragma unroll
            for (int r = 0; r < 4; r++) acc[i][j][r] = 0.f;

    for (int c = 0; c < 32; c++) {
        const int k0 = c * 32;
        __syncthreads();    // previous iter's mma reads done

        // ---- A tile: 128x32 floats -> tf32, fragment layout ----
        #pragma unroll
        for (int i = 0; i < 4; i++) {
            int id  = tid + i * 256;         // 0..1023 float4s
            int row = id >> 3, kq = id & 7;  // kq: which 4-wide k group
            float4 a4 = *(const float4*)(A + (size_t)(m0 + row) * D_ + k0 + (kq << 2));
            int mt = row >> 4, mi = row & 15;
            int ks = kq >> 1, kp = kq & 1;
            int reg = (mi >> 3) + 2 * kp;
            int lb  = (mi & 7) << 2;
            uint32_t* p = &As[(((mt * 4 + ks) * 32) << 2) + reg];
            p[(lb + 0) << 2] = cvt_tf32(a4.x);
            p[(lb + 1) << 2] = cvt_tf32(a4.y);
            p[(lb + 2) << 2] = cvt_tf32(a4.z);
            p[(lb + 3) << 2] = cvt_tf32(a4.w);
        }
        // ---- B tile: 128(n) x 32(k), already tf32 bits ----
        #pragma unroll
        for (int i = 0; i < 4; i++) {
            int id  = tid + i * 256;
            int row = id >> 3, kq = id & 7;
            uint4 b4 = *(const uint4*)(Wt + (size_t)(n0 + row) * D_ + k0 + (kq << 2));
            int nt = row >> 3, ni = row & 7;
            int ks = kq >> 1, kp = kq & 1;
            uint32_t* p = &Bs[(((nt * 4 + ks) * 32) << 1) + kp];
            p[(ni * 4 + 0) << 1] = b4.x;
            p[(ni * 4 + 1) << 1] = b4.y;
            p[(ni * 4 + 2) << 1] = b4.z;
            p[(ni * 4 + 3) << 1] = b4.w;
        }
        __syncthreads();

        // ---- 4 k-steps of m16n8k8 ----
        #pragma unroll
        for (int ks = 0; ks < 4; ks++) {
            uint4 af[4]; uint2 bf[4];
            #pragma unroll
            for (int mt = 0; mt < 4; mt++)
                af[mt] = *(const uint4*)&As[((((wm * 4 + mt) * 4 + ks) * 32 + lane) << 2)];
            #pragma unroll
            for (int nt = 0; nt < 4; nt++)
                bf[nt] = *(const uint2*)&Bs[((((wn * 4 + nt) * 4 + ks) * 32 + lane) << 1)];
            #pragma unroll
            for (int mt = 0; mt < 4; mt++)
                #pragma unroll
                for (int nt = 0; nt < 4; nt++)
                    mma_tf32(acc[mt][nt], (const uint32_t*)&af[mt], (const uint32_t*)&bf[nt]);
        }
    }

    // ---- epilogue: D-fragment layout -> gmem + bias ----
    const int gm = m0 + wm * 64;
    const int gn = n0 + wn * 32;
    const int r4 = lane >> 2, c2 = (lane & 3) << 1;
    #pragma unroll
    for (int nt = 0; nt < 4; nt++) {
        const int col = gn + nt * 8 + c2;
        float2 bb = *(const float2*)(bias + col);
        #pragma unroll
        for (int mt = 0; mt < 4; mt++) {
            const int row = gm + mt * 16 + r4;
            float2 lo = {acc[mt][nt][0] + bb.x, acc[mt][nt][1] + bb.y};
            float2 hi = {acc[mt][nt][2] + bb.x, acc[mt][nt][3] + bb.y};
            *(float2*)(C + (size_t)row * D_ + col)       = lo;
            *(float2*)(C + (size_t)(row + 8) * D_ + col) = hi;
        }
    }
}

// ---------------- causal flash attention, 64x64 tiles, fp32 ---------------
__global__ __launch_bounds__(256, 2)
void flash_kernel(const float* __restrict__ q, const float* __restrict__ k,
                  const float* __restrict__ v, float* __restrict__ o)
{
    __shared__ float Qs[64 * 64];
    __shared__ float Ks[64 * 64];
    __shared__ float Vs[64 * 64];
    float* Ps = Ks;   // overlay

    const int qt = blockIdx.x, h = blockIdx.y, b = blockIdx.z;
    const int tid = threadIdx.x;
    const int tx = tid & 15, ty = tid >> 4;

    const size_t base = (size_t)b * S_ * D_ + (size_t)h * DK_;
    const float* qg = q + base + (size_t)qt * 64 * D_;

    for (int it = tid; it < 64 * 16; it += 256) {
        int r = it >> 4, c4 = (it & 15) << 2;
        *(float4*)&Qs[r * 64 + c4] = *(const float4*)(qg + (size_t)r * D_ + c4);
    }

    float m_i[4], l_i[4];
    u64 o2[4][2];
    #pragma unroll
    for (int i = 0; i < 4; i++) {
        m_i[i] = -1e30f; l_i[i] = 0.f; o2[i][0] = 0ull; o2[i][1] = 0ull;
    }

    for (int kt = 0; kt <= qt; kt++) {
        const float* kg = k + base + (size_t)kt * 64 * D_;
        const float* vg = v + base + (size_t)kt * 64 * D_;
        __syncthreads();
        for (int it = tid; it < 64 * 16; it += 256) {
            int r = it >> 4, c4 = it & 15;
            float4 kvv = *(const float4*)(kg + (size_t)r * D_ + (c4 << 2));
            Ks[r * 64 + (((c4 ^ (r & 15))) << 2) + 0] = kvv.x;
            Ks[r * 64 + (((c4 ^ (r & 15))) << 2) + 1] = kvv.y;
            Ks[r * 64 + (((c4 ^ (r & 15))) << 2) + 2] = kvv.z;
            Ks[r * 64 + (((c4 ^ (r & 15))) << 2) + 3] = kvv.w;
            *(float4*)&Vs[r * 64 + (c4 << 2)] =
                *(const float4*)(vg + (size_t)r * D_ + (c4 << 2));
        }
        __syncthreads();

        u64 s2[4][4];
        #pragma unroll
        for (int i = 0; i < 4; i++)
            #pragma unroll
            for (int j = 0; j < 4; j++) s2[i][j] = 0ull;

        #pragma unroll 4
        for (int d = 0; d < 64; d += 4) {
            ulonglong2 q2[4], k2[4];
            #pragma unroll
            for (int i = 0; i < 4; i++)
                q2[i] = *(const ulonglong2*)&Qs[(ty * 4 + i) * 64 + d];
            const int sgo = (((d >> 2) ^ tx) << 2);
            #pragma unroll
            for (int j = 0; j < 4; j++)
                k2[j] = *(const ulonglong2*)&Ks[(tx + 16 * j) * 64 + sgo];
            #pragma unroll
            for (int i = 0; i < 4; i++)
                #pragma unroll
                for (int j = 0; j < 4; j++) {
                    f32x2_fma(s2[i][j], q2[i].x, k2[j].x);
                    f32x2_fma(s2[i][j], q2[i].y, k2[j].y);
                }
        }
        __syncthreads();

        float st[4][4];
        #pragma unroll
        for (int i = 0; i < 4; i++)
            #pragma unroll
            for (int j = 0; j < 4; j++) {
                float lo, hi; f32x2_unpack(s2[i][j], lo, hi);
                st[i][j] = (lo + hi) * 0.125f;
            }
        if (kt == qt) {
            #pragma unroll
            for (int i = 0; i < 4; i++)
                #pragma unroll
                for (int j = 0; j < 4; j++)
                    if (tx + 16 * j > ty * 4 + i) st[i][j] = -1e30f;
        }

        #pragma unroll
        for (int i = 0; i < 4; i++) {
            float tm = fmaxf(fmaxf(st[i][0], st[i][1]), fmaxf(st[i][2], st[i][3]));
            #pragma unroll
            for (int off = 8; off >= 1; off >>= 1)
                tm = fmaxf(tm, __shfl_xor_sync(0xffffffffu, tm, off));
            float mnew = fmaxf(m_i[i], tm);
            float corr = __expf(m_i[i] - mnew);
            m_i[i] = mnew;
            float rs = 0.f;
            #pragma unroll
            for (int j = 0; j < 4; j++) {
                float p = __expf(st[i][j] - mnew);
                Ps[(ty * 4 + i) * 64 + tx + 16 * j] = p;
                rs += p;
            }
            #pragma unroll
            for (int off = 8; off >= 1; off >>= 1)
                rs += __shfl_xor_sync(0xffffffffu, rs, off);
            l_i[i] = l_i[i] * corr + rs;
            u64 c2 = f32x2_dup(corr);
            f32x2_mul(o2[i][0], o2[i][0], c2);
            f32x2_mul(o2[i][1], o2[i][1], c2);
        }
        __syncthreads();

        #pragma unroll 2
        for (int j4 = 0; j4 < 16; j4++) {
            float pr[4][4];
            #pragma unroll
            for (int i = 0; i < 4; i++) {
                float4 p4 = *(const float4*)&Ps[(ty * 4 + i) * 64 + (j4 << 2)];
                pr[i][0] = p4.x; pr[i][1] = p4.y; pr[i][2] = p4.z; pr[i][3] = p4.w;
            }
            #pragma unroll
            for (int jj = 0; jj < 4; jj++) {
                ulonglong2 vv = *(const ulonglong2*)&Vs[((j4 << 2) + jj) * 64 + (tx << 2)];
                #pragma unroll
                for (int i = 0; i < 4; i++) {
                    u64 p2 = f32x2_dup(pr[i][jj]);
                    f32x2_fma(o2[i][0], p2, vv.x);
                    f32x2_fma(o2[i][1], p2, vv.y);
                }
            }
        }
    }

    float* og = o + base + (size_t)qt * 64 * D_;
    #pragma unroll
    for (int i = 0; i < 4; i++) {
        float inv = 1.f / l_i[i];
        float lo0, hi0, lo1, hi1;
        f32x2_unpack(o2[i][0], lo0, hi0);
        f32x2_unpack(o2[i][1], lo1, hi1);
        float4 res = {lo0 * inv, hi0 * inv, lo1 * inv, hi1 * inv};
        *(float4*)(og + (size_t)(ty * 4 + i) * D_ + (tx << 2)) = res;
    }
}

// ---------------- launch ---------------------------------------------------
extern "C" void kernel_launch(void* const* d_in, const int* in_sizes, int n_in,
                              void* d_out, int out_size)
{
    (void)in_sizes; (void)n_in; (void)out_size;
    const float* Qin  = (const float*)d_in[0];
    const float* KVin = (const float*)d_in[1];
    // d_in[2] = mask (causal by construction; handled analytically)
    const float* Wq = (const float*)d_in[3];
    const float* bq = (const float*)d_in[4];
    const float* Wk = (const float*)d_in[5];
    const float* bk = (const float*)d_in[6];
    const float* Wv = (const float*)d_in[7];
    const float* bv = (const float*)d_in[8];
    const float* Wo = (const float*)d_in[9];
    const float* bo = (const float*)d_in[10];
    float* out = (float*)d_out;

    float *gq, *gk, *gv, *ga, *gwt;
    cudaGetSymbolAddress((void**)&gq,  g_q);
    cudaGetSymbolAddress((void**)&gk,  g_k);
    cudaGetSymbolAddress((void**)&gv,  g_v);
    cudaGetSymbolAddress((void**)&ga,  g_att);
    cudaGetSymbolAddress((void**)&gwt, g_wt);
    float* wt0 = gwt;
    float* wt1 = gwt + (size_t)D_ * D_;
    float* wt2 = gwt + 2 * (size_t)D_ * D_;
    float* wt3 = gwt + 3 * (size_t)D_ * D_;

    dim3 tb(32, 8), tg(32, 32);
    transpose_tf32_kernel<<<tg, tb>>>(Wq, wt0);
    transpose_tf32_kernel<<<tg, tb>>>(Wk, wt1);
    transpose_tf32_kernel<<<tg, tb>>>(Wv, wt2);
    transpose_tf32_kernel<<<tg, tb>>>(Wo, wt3);

    dim3 gg(D_ / 128, M_ / 128);
    gemm_mma_kernel<<<gg, 256>>>(Qin,  wt0, bq, gq);
    gemm_mma_kernel<<<gg, 256>>>(KVin, wt1, bk, gk);
    gemm_mma_kernel<<<gg, 256>>>(KVin, wt2, bv, gv);

    dim3 fg(S_ / 64, H_, B_);
    flash_kernel<<<fg, 256>>>(gq, gk, gv, ga);

    gemm_mma_kernel<<<gg, 256>>>(ga, wt3, bo, out);
}

// round 12
// speedup vs baseline: 1.4654x; 1.4654x over previous
#include <cuda_runtime.h>
#include <cstdint>

#define B_  4
#define S_  2048
#define D_  1024
#define H_  16
#define DK_ 64
#define M_  (B_*S_)   // 8192 rows

// ---------------- scratch (device globals: no allocation allowed) ----------
__device__ float g_q  [(size_t)M_ * D_];
__device__ float g_k  [(size_t)M_ * D_];
__device__ float g_v  [(size_t)M_ * D_];
__device__ float g_att[(size_t)M_ * D_];
__device__ float g_wt [4][(size_t)D_ * D_];   // W transposed + tf32-rounded

// ---------------- f32x2 packed helpers (full-rate fp32 on sm_103a) --------
typedef unsigned long long u64;

__device__ __forceinline__ u64 f32x2_dup(float a) {
    u64 r; asm("mov.b64 %0, {%1, %1};" : "=l"(r) : "f"(a)); return r;
}
__device__ __forceinline__ void f32x2_unpack(u64 v, float& lo, float& hi) {
    asm("mov.b64 {%0, %1}, %2;" : "=f"(lo), "=f"(hi) : "l"(v));
}
__device__ __forceinline__ void f32x2_fma(u64& d, u64 a, u64 b) {
    asm("fma.rn.f32x2 %0, %1, %2, %3;" : "=l"(d) : "l"(a), "l"(b), "l"(d));
}
__device__ __forceinline__ void f32x2_mul(u64& d, u64 a, u64 b) {
    asm("mul.rn.f32x2 %0, %1, %2;" : "=l"(d) : "l"(a), "l"(b));
}

__device__ __forceinline__ uint32_t cvt_tf32(float f) {
    uint32_t u; asm("cvt.rna.tf32.f32 %0, %1;" : "=r"(u) : "f"(f)); return u;
}
__device__ __forceinline__ uint32_t smem_u32(const void* p) {
    uint32_t a;
    asm("{ .reg .u64 t; cvta.to.shared.u64 t, %1; cvt.u32.u64 %0, t; }"
        : "=r"(a) : "l"(p));
    return a;
}
__device__ __forceinline__ void cp_async16(uint32_t smem_addr, const void* gptr) {
    asm volatile("cp.async.ca.shared.global [%0], [%1], 16;"
                 :: "r"(smem_addr), "l"(gptr) : "memory");
}
#define CP_COMMIT()  asm volatile("cp.async.commit_group;" ::: "memory")
#define CP_WAIT0()   asm volatile("cp.async.wait_group 0;" ::: "memory")

// mma.sync m16n8k8 tf32 (legacy tensor-core path; valid on compute_103)
__device__ __forceinline__ void mma_tf32(float* c, const uint32_t* a, const uint32_t* b) {
    asm volatile(
        "mma.sync.aligned.m16n8k8.row.col.f32.tf32.tf32.f32 "
        "{%0,%1,%2,%3}, {%4,%5,%6,%7}, {%8,%9}, {%0,%1,%2,%3};"
        : "+f"(c[0]), "+f"(c[1]), "+f"(c[2]), "+f"(c[3])
        : "r"(a[0]), "r"(a[1]), "r"(a[2]), "r"(a[3]), "r"(b[0]), "r"(b[1]));
}

// SW128-style swizzle helpers for 128B-row tiles (BK=32 floats).
// store: float4 at (row, granule kq): word = row*32 + ((kq ^ (row&7))<<2)
// load:  element (row, k):            word = row*32 + (((k>>2) ^ (row&7))<<2) + (k&3)
__device__ __forceinline__ int swz_st(int row, int kq) {
    return row * 32 + ((kq ^ (row & 7)) << 2);
}
__device__ __forceinline__ int swz_ld(int row, int k) {
    return row * 32 + (((k >> 2) ^ (row & 7)) << 2) + (k & 3);
}

// ---------------- W transpose + tf32 round: Wt[n][k] = tf32(W[k][n]) -------
__global__ void transpose_tf32_kernel(const float* __restrict__ W,
                                      float* __restrict__ Wt)
{
    __shared__ float t[32][33];
    const int tx = threadIdx.x, ty = threadIdx.y;       // 32 x 8
    const int nb = blockIdx.x * 32, kb = blockIdx.y * 32;
    #pragma unroll
    for (int i = 0; i < 32; i += 8)
        t[ty + i][tx] = W[(size_t)(kb + ty + i) * D_ + nb + tx];
    __syncthreads();
    #pragma unroll
    for (int i = 0; i < 32; i += 8) {
        uint32_t v = cvt_tf32(t[tx][ty + i]);
        Wt[(size_t)(nb + ty + i) * D_ + kb + tx] = __uint_as_float(v);
    }
}

// ---------------- mma.sync tf32 GEMM, double-buffered, swizzled -----------
// CTA 128x128, BK=32. 8 warps as 2(m) x 4(n); warp tile 64x32 = 4x4 m16n8k8.
// A: LDG->regs prefetch + cvt.tf32 + STS.128 (swizzled, conflict-free).
// B: cp.async (weights pre-converted to tf32 by transpose kernel).
// Dynamic smem: 2 x (16KB A + 16KB B) = 64KB.
__global__ __launch_bounds__(256, 2)
void gemm_mma_kernel(const float* __restrict__ A, const float* __restrict__ Wt,
                     const float* __restrict__ bias, float* __restrict__ C)
{
    extern __shared__ uint32_t sm[];
    uint32_t* Asm[2] = { sm,        sm + 4096 };
    uint32_t* Bsm[2] = { sm + 8192, sm + 12288 };
    const uint32_t b_smem0 = smem_u32(sm + 8192);
    const uint32_t b_smem1 = smem_u32(sm + 12288);

    const int tid  = threadIdx.x;
    const int wid  = tid >> 5, lane = tid & 31;
    const int m0 = blockIdx.y * 128, n0 = blockIdx.x * 128;
    const int wm = wid >> 2, wn = wid & 3;    // warp grid 2 x 4
    const int g  = lane >> 2, cc = lane & 3;  // fragment coords

    // per-thread tile coords: 4 float4 chunks per matrix per BK=32 chunk
    int lrow[4], lkq[4];
    #pragma unroll
    for (int i = 0; i < 4; i++) {
        int id = tid + i * 256;
        lrow[i] = id >> 3;
        lkq[i]  = id & 7;
    }

    float acc[4][4][4];
    #pragma unroll
    for (int i = 0; i < 4; i++)
        #pragma unroll
        for (int j = 0; j < 4; j++)
            #pragma unroll
            for (int r = 0; r < 4; r++) acc[i][j][r] = 0.f;

    // ---- prologue: chunk 0 into buffer 0 ----
    float4 ar[4];
    #pragma unroll
    for (int i = 0; i < 4; i++)
        cp_async16(b_smem0 + swz_st(lrow[i], lkq[i]) * 4,
                   Wt + (size_t)(n0 + lrow[i]) * D_ + lkq[i] * 4);
    CP_COMMIT();
    #pragma unroll
    for (int i = 0; i < 4; i++)
        ar[i] = *(const float4*)(A + (size_t)(m0 + lrow[i]) * D_ + lkq[i] * 4);
    #pragma unroll
    for (int i = 0; i < 4; i++) {
        uint4 u;
        u.x = cvt_tf32(ar[i].x); u.y = cvt_tf32(ar[i].y);
        u.z = cvt_tf32(ar[i].z); u.w = cvt_tf32(ar[i].w);
        *(uint4*)&Asm[0][swz_st(lrow[i], lkq[i])] = u;
    }
    CP_WAIT0();
    __syncthreads();

    for (int c = 0; c < 32; c++) {
        const int cur = c & 1, nxt = cur ^ 1;
        const int k1 = (c + 1) * 32;

        // prefetch chunk c+1
        if (c < 31) {
            const uint32_t bdst = (nxt ? b_smem1 : b_smem0);
            #pragma unroll
            for (int i = 0; i < 4; i++)
                cp_async16(bdst + swz_st(lrow[i], lkq[i]) * 4,
                           Wt + (size_t)(n0 + lrow[i]) * D_ + k1 + lkq[i] * 4);
            CP_COMMIT();
            #pragma unroll
            for (int i = 0; i < 4; i++)
                ar[i] = *(const float4*)(A + (size_t)(m0 + lrow[i]) * D_ + k1 + lkq[i] * 4);
        }

        // ---- compute chunk c: 4 k-steps of m16n8k8 ----
        const uint32_t* Ab = Asm[cur];
        const uint32_t* Bb = Bsm[cur];
        #pragma unroll
        for (int ks = 0; ks < 4; ks++) {
            const int kk = ks * 8 + cc;
            uint32_t af[4][4], bf[4][2];
            #pragma unroll
            for (int mt = 0; mt < 4; mt++) {
                const int r = wm * 64 + mt * 16 + g;
                af[mt][0] = Ab[swz_ld(r,     kk)];
                af[mt][1] = Ab[swz_ld(r + 8, kk)];
                af[mt][2] = Ab[swz_ld(r,     kk + 4)];
                af[mt][3] = Ab[swz_ld(r + 8, kk + 4)];
            }
            #pragma unroll
            for (int nt = 0; nt < 4; nt++) {
                const int n = wn * 32 + nt * 8 + g;
                bf[nt][0] = Bb[swz_ld(n, kk)];
                bf[nt][1] = Bb[swz_ld(n, kk + 4)];
            }
            #pragma unroll
            for (int mt = 0; mt < 4; mt++)
                #pragma unroll
                for (int nt = 0; nt < 4; nt++)
                    mma_tf32(acc[mt][nt], af[mt], bf[nt]);
        }

        // store prefetched A into next buffer
        if (c < 31) {
            uint32_t* An = Asm[nxt];
            #pragma unroll
            for (int i = 0; i < 4; i++) {
                uint4 u;
                u.x = cvt_tf32(ar[i].x); u.y = cvt_tf32(ar[i].y);
                u.z = cvt_tf32(ar[i].z); u.w = cvt_tf32(ar[i].w);
                *(uint4*)&An[swz_st(lrow[i], lkq[i])] = u;
            }
        }
        CP_WAIT0();
        __syncthreads();
    }

    // ---- epilogue: D-fragment layout -> gmem + bias (verified in R10) ----
    const int gm = m0 + wm * 64;
    const int gn = n0 + wn * 32;
    const int r4 = lane >> 2, c2 = (lane & 3) << 1;
    #pragma unroll
    for (int nt = 0; nt < 4; nt++) {
        const int col = gn + nt * 8 + c2;
        float2 bb = *(const float2*)(bias + col);
        #pragma unroll
        for (int mt = 0; mt < 4; mt++) {
            const int row = gm + mt * 16 + r4;
            float2 lo = {acc[mt][nt][0] + bb.x, acc[mt][nt][1] + bb.y};
            float2 hi = {acc[mt][nt][2] + bb.x, acc[mt][nt][3] + bb.y};
            *(float2*)(C + (size_t)row * D_ + col)       = lo;
            *(float2*)(C + (size_t)(row + 8) * D_ + col) = hi;
        }
    }
}

// ---------------- causal flash attention, 64x64 tiles, fp32 ---------------
__global__ __launch_bounds__(256, 2)
void flash_kernel(const float* __restrict__ q, const float* __restrict__ k,
                  const float* __restrict__ v, float* __restrict__ o)
{
    __shared__ float Qs[64 * 64];
    __shared__ float Ks[64 * 64];
    __shared__ float Vs[64 * 64];
    float* Ps = Ks;   // overlay

    const int qt = blockIdx.x, h = blockIdx.y, b = blockIdx.z;
    const int tid = threadIdx.x;
    const int tx = tid & 15, ty = tid >> 4;

    const size_t base = (size_t)b * S_ * D_ + (size_t)h * DK_;
    const float* qg = q + base + (size_t)qt * 64 * D_;

    for (int it = tid; it < 64 * 16; it += 256) {
        int r = it >> 4, c4 = (it & 15) << 2;
        *(float4*)&Qs[r * 64 + c4] = *(const float4*)(qg + (size_t)r * D_ + c4);
    }

    float m_i[4], l_i[4];
    u64 o2[4][2];
    #pragma unroll
    for (int i = 0; i < 4; i++) {
        m_i[i] = -1e30f; l_i[i] = 0.f; o2[i][0] = 0ull; o2[i][1] = 0ull;
    }

    for (int kt = 0; kt <= qt; kt++) {
        const float* kg = k + base + (size_t)kt * 64 * D_;
        const float* vg = v + base + (size_t)kt * 64 * D_;
        __syncthreads();
        for (int it = tid; it < 64 * 16; it += 256) {
            int r = it >> 4, c4 = it & 15;
            float4 kvv = *(const float4*)(kg + (size_t)r * D_ + (c4 << 2));
            Ks[r * 64 + (((c4 ^ (r & 15))) << 2) + 0] = kvv.x;
            Ks[r * 64 + (((c4 ^ (r & 15))) << 2) + 1] = kvv.y;
            Ks[r * 64 + (((c4 ^ (r & 15))) << 2) + 2] = kvv.z;
            Ks[r * 64 + (((c4 ^ (r & 15))) << 2) + 3] = kvv.w;
            *(float4*)&Vs[r * 64 + (c4 << 2)] =
                *(const float4*)(vg + (size_t)r * D_ + (c4 << 2));
        }
        __syncthreads();

        u64 s2[4][4];
        #pragma unroll
        for (int i = 0; i < 4; i++)
            #pragma unroll
            for (int j = 0; j < 4; j++) s2[i][j] = 0ull;

        #pragma unroll 4
        for (int d = 0; d < 64; d += 4) {
            ulonglong2 q2[4], k2[4];
            #pragma unroll
            for (int i = 0; i < 4; i++)
                q2[i] = *(const ulonglong2*)&Qs[(ty * 4 + i) * 64 + d];
            const int sgo = (((d >> 2) ^ tx) << 2);
            #pragma unroll
            for (int j = 0; j < 4; j++)
                k2[j] = *(const ulonglong2*)&Ks[(tx + 16 * j) * 64 + sgo];
            #pragma unroll
            for (int i = 0; i < 4; i++)
                #pragma unroll
                for (int j = 0; j < 4; j++) {
                    f32x2_fma(s2[i][j], q2[i].x, k2[j].x);
                    f32x2_fma(s2[i][j], q2[i].y, k2[j].y);
                }
        }
        __syncthreads();

        float st[4][4];
        #pragma unroll
        for (int i = 0; i < 4; i++)
            #pragma unroll
            for (int j = 0; j < 4; j++) {
                float lo, hi; f32x2_unpack(s2[i][j], lo, hi);
                st[i][j] = (lo + hi) * 0.125f;
            }
        if (kt == qt) {
            #pragma unroll
            for (int i = 0; i < 4; i++)
                #pragma unroll
                for (int j = 0; j < 4; j++)
                    if (tx + 16 * j > ty * 4 + i) st[i][j] = -1e30f;
        }

        #pragma unroll
        for (int i = 0; i < 4; i++) {
            float tm = fmaxf(fmaxf(st[i][0], st[i][1]), fmaxf(st[i][2], st[i][3]));
            #pragma unroll
            for (int off = 8; off >= 1; off >>= 1)
                tm = fmaxf(tm, __shfl_xor_sync(0xffffffffu, tm, off));
            float mnew = fmaxf(m_i[i], tm);
            float corr = __expf(m_i[i] - mnew);
            m_i[i] = mnew;
            float rs = 0.f;
            #pragma unroll
            for (int j = 0; j < 4; j++) {
                float p = __expf(st[i][j] - mnew);
                Ps[(ty * 4 + i) * 64 + tx + 16 * j] = p;
                rs += p;
            }
            #pragma unroll
            for (int off = 8; off >= 1; off >>= 1)
                rs += __shfl_xor_sync(0xffffffffu, rs, off);
            l_i[i] = l_i[i] * corr + rs;
            u64 c2 = f32x2_dup(corr);
            f32x2_mul(o2[i][0], o2[i][0], c2);
            f32x2_mul(o2[i][1], o2[i][1], c2);
        }
        __syncthreads();

        #pragma unroll 2
        for (int j4 = 0; j4 < 16; j4++) {
            float pr[4][4];
            #pragma unroll
            for (int i = 0; i < 4; i++) {
                float4 p4 = *(const float4*)&Ps[(ty * 4 + i) * 64 + (j4 << 2)];
                pr[i][0] = p4.x; pr[i][1] = p4.y; pr[i][2] = p4.z; pr[i][3] = p4.w;
            }
            #pragma unroll
            for (int jj = 0; jj < 4; jj++) {
                ulonglong2 vv = *(const ulonglong2*)&Vs[((j4 << 2) + jj) * 64 + (tx << 2)];
                #pragma unroll
                for (int i = 0; i < 4; i++) {
                    u64 p2 = f32x2_dup(pr[i][jj]);
                    f32x2_fma(o2[i][0], p2, vv.x);
                    f32x2_fma(o2[i][1], p2, vv.y);
                }
            }
        }
    }

    float* og = o + base + (size_t)qt * 64 * D_;
    #pragma unroll
    for (int i = 0; i < 4; i++) {
        float inv = 1.f / l_i[i];
        float lo0, hi0, lo1, hi1;
        f32x2_unpack(o2[i][0], lo0, hi0);
        f32x2_unpack(o2[i][1], lo1, hi1);
        float4 res = {lo0 * inv, hi0 * inv, lo1 * inv, hi1 * inv};
        *(float4*)(og + (size_t)(ty * 4 + i) * D_ + (tx << 2)) = res;
    }
}

// ---------------- launch ---------------------------------------------------
extern "C" void kernel_launch(void* const* d_in, const int* in_sizes, int n_in,
                              void* d_out, int out_size)
{
    (void)in_sizes; (void)n_in; (void)out_size;
    const float* Qin  = (const float*)d_in[0];
    const float* KVin = (const float*)d_in[1];
    // d_in[2] = mask (causal by construction; handled analytically)
    const float* Wq = (const float*)d_in[3];
    const float* bq = (const float*)d_in[4];
    const float* Wk = (const float*)d_in[5];
    const float* bk = (const float*)d_in[6];
    const float* Wv = (const float*)d_in[7];
    const float* bv = (const float*)d_in[8];
    const float* Wo = (const float*)d_in[9];
    const float* bo = (const float*)d_in[10];
    float* out = (float*)d_out;

    float *gq, *gk, *gv, *ga, *gwt;
    cudaGetSymbolAddress((void**)&gq,  g_q);
    cudaGetSymbolAddress((void**)&gk,  g_k);
    cudaGetSymbolAddress((void**)&gv,  g_v);
    cudaGetSymbolAddress((void**)&ga,  g_att);
    cudaGetSymbolAddress((void**)&gwt, g_wt);
    float* wt0 = gwt;
    float* wt1 = gwt + (size_t)D_ * D_;
    float* wt2 = gwt + 2 * (size_t)D_ * D_;
    float* wt3 = gwt + 3 * (size_t)D_ * D_;

    static int smem_set = 0;
    if (!smem_set) {
        cudaFuncSetAttribute(gemm_mma_kernel,
                             cudaFuncAttributeMaxDynamicSharedMemorySize, 65536);
        smem_set = 1;
    }

    dim3 tb(32, 8), tg(32, 32);
    transpose_tf32_kernel<<<tg, tb>>>(Wq, wt0);
    transpose_tf32_kernel<<<tg, tb>>>(Wk, wt1);
    transpose_tf32_kernel<<<tg, tb>>>(Wv, wt2);
    transpose_tf32_kernel<<<tg, tb>>>(Wo, wt3);

    dim3 gg(D_ / 128, M_ / 128);
    gemm_mma_kernel<<<gg, 256, 65536>>>(Qin,  wt0, bq, gq);
    gemm_mma_kernel<<<gg, 256, 65536>>>(KVin, wt1, bk, gk);
    gemm_mma_kernel<<<gg, 256, 65536>>>(KVin, wt2, bv, gv);

    dim3 fg(S_ / 64, H_, B_);
    flash_kernel<<<fg, 256>>>(gq, gk, gv, ga);

    gemm_mma_kernel<<<gg, 256, 65536>>>(ga, wt3, bo, out);
}

// round 13
// speedup vs baseline: 2.1469x; 1.4651x over previous
#include <cuda_runtime.h>
#include <cstdint>

#define B_  4
#define S_  2048
#define D_  1024
#define H_  16
#define DK_ 64
#define M_  (B_*S_)   // 8192 rows

// ---------------- scratch (device globals: no allocation allowed) ----------
__device__ float g_q  [(size_t)M_ * D_];
__device__ float g_k  [(size_t)M_ * D_];
__device__ float g_v  [(size_t)M_ * D_];
__device__ float g_att[(size_t)M_ * D_];
__device__ float g_wt [4][(size_t)D_ * D_];   // W transposed + tf32-rounded

typedef unsigned long long u64;

__device__ __forceinline__ uint32_t cvt_tf32(float f) {
    uint32_t u; asm("cvt.rna.tf32.f32 %0, %1;" : "=r"(u) : "f"(f)); return u;
}
__device__ __forceinline__ uint32_t smem_u32(const void* p) {
    uint32_t a;
    asm("{ .reg .u64 t; cvta.to.shared.u64 t, %1; cvt.u32.u64 %0, t; }"
        : "=r"(a) : "l"(p));
    return a;
}
__device__ __forceinline__ void cp_async16(uint32_t smem_addr, const void* gptr) {
    asm volatile("cp.async.ca.shared.global [%0], [%1], 16;"
                 :: "r"(smem_addr), "l"(gptr) : "memory");
}
#define CP_COMMIT()  asm volatile("cp.async.commit_group;" ::: "memory")
#define CP_WAIT0()   asm volatile("cp.async.wait_group 0;" ::: "memory")

// mma.sync m16n8k8 tf32 (legacy tensor-core path; valid on compute_103)
__device__ __forceinline__ void mma_tf32(float* c, const uint32_t* a, const uint32_t* b) {
    asm volatile(
        "mma.sync.aligned.m16n8k8.row.col.f32.tf32.tf32.f32 "
        "{%0,%1,%2,%3}, {%4,%5,%6,%7}, {%8,%9}, {%0,%1,%2,%3};"
        : "+f"(c[0]), "+f"(c[1]), "+f"(c[2]), "+f"(c[3])
        : "r"(a[0]), "r"(a[1]), "r"(a[2]), "r"(a[3]), "r"(b[0]), "r"(b[1]));
}

// swizzle for 32-float (BK=32) rows — used by GEMM
__device__ __forceinline__ int swz_st(int row, int kq) {
    return row * 32 + ((kq ^ (row & 7)) << 2);
}
__device__ __forceinline__ int swz_ld(int row, int k) {
    return row * 32 + (((k >> 2) ^ (row & 7)) << 2) + (k & 3);
}
// swizzle for 64-float rows — used by flash tiles
__device__ __forceinline__ int swz_st64(int row, int c4) {
    return row * 64 + ((c4 ^ (row & 15)) << 2);
}
__device__ __forceinline__ int swz_ld64(int row, int k) {
    return row * 64 + ((((k >> 2) ^ (row & 15)) & 15) << 2) + (k & 3);
}

// ---------------- W transpose + tf32 round: Wt[n][k] = tf32(W[k][n]) -------
__global__ void transpose_tf32_kernel(const float* __restrict__ W,
                                      float* __restrict__ Wt)
{
    __shared__ float t[32][33];
    const int tx = threadIdx.x, ty = threadIdx.y;       // 32 x 8
    const int nb = blockIdx.x * 32, kb = blockIdx.y * 32;
    #pragma unroll
    for (int i = 0; i < 32; i += 8)
        t[ty + i][tx] = W[(size_t)(kb + ty + i) * D_ + nb + tx];
    __syncthreads();
    #pragma unroll
    for (int i = 0; i < 32; i += 8) {
        uint32_t v = cvt_tf32(t[tx][ty + i]);
        Wt[(size_t)(nb + ty + i) * D_ + kb + tx] = __uint_as_float(v);
    }
}

// ---------------- mma.sync tf32 GEMM, double-buffered, swizzled (R12) -----
__global__ __launch_bounds__(256, 2)
void gemm_mma_kernel(const float* __restrict__ A, const float* __restrict__ Wt,
                     const float* __restrict__ bias, float* __restrict__ C)
{
    extern __shared__ uint32_t sm[];
    uint32_t* Asm[2] = { sm,        sm + 4096 };
    uint32_t* Bsm[2] = { sm + 8192, sm + 12288 };
    const uint32_t b_smem0 = smem_u32(sm + 8192);
    const uint32_t b_smem1 = smem_u32(sm + 12288);

    const int tid  = threadIdx.x;
    const int wid  = tid >> 5, lane = tid & 31;
    const int m0 = blockIdx.y * 128, n0 = blockIdx.x * 128;
    const int wm = wid >> 2, wn = wid & 3;
    const int g  = lane >> 2, cc = lane & 3;

    int lrow[4], lkq[4];
    #pragma unroll
    for (int i = 0; i < 4; i++) {
        int id = tid + i * 256;
        lrow[i] = id >> 3;
        lkq[i]  = id & 7;
    }

    float acc[4][4][4];
    #pragma unroll
    for (int i = 0; i < 4; i++)
        #pragma unroll
        for (int j = 0; j < 4; j++)
            #pragma unroll
            for (int r = 0; r < 4; r++) acc[i][j][r] = 0.f;

    float4 ar[4];
    #pragma unroll
    for (int i = 0; i < 4; i++)
        cp_async16(b_smem0 + swz_st(lrow[i], lkq[i]) * 4,
                   Wt + (size_t)(n0 + lrow[i]) * D_ + lkq[i] * 4);
    CP_COMMIT();
    #pragma unroll
    for (int i = 0; i < 4; i++)
        ar[i] = *(const float4*)(A + (size_t)(m0 + lrow[i]) * D_ + lkq[i] * 4);
    #pragma unroll
    for (int i = 0; i < 4; i++) {
        uint4 u;
        u.x = cvt_tf32(ar[i].x); u.y = cvt_tf32(ar[i].y);
        u.z = cvt_tf32(ar[i].z); u.w = cvt_tf32(ar[i].w);
        *(uint4*)&Asm[0][swz_st(lrow[i], lkq[i])] = u;
    }
    CP_WAIT0();
    __syncthreads();

    for (int c = 0; c < 32; c++) {
        const int cur = c & 1, nxt = cur ^ 1;
        const int k1 = (c + 1) * 32;

        if (c < 31) {
            const uint32_t bdst = (nxt ? b_smem1 : b_smem0);
            #pragma unroll
            for (int i = 0; i < 4; i++)
                cp_async16(bdst + swz_st(lrow[i], lkq[i]) * 4,
                           Wt + (size_t)(n0 + lrow[i]) * D_ + k1 + lkq[i] * 4);
            CP_COMMIT();
            #pragma unroll
            for (int i = 0; i < 4; i++)
                ar[i] = *(const float4*)(A + (size_t)(m0 + lrow[i]) * D_ + k1 + lkq[i] * 4);
        }

        const uint32_t* Ab = Asm[cur];
        const uint32_t* Bb = Bsm[cur];
        #pragma unroll
        for (int ks = 0; ks < 4; ks++) {
            const int kk = ks * 8 + cc;
            uint32_t af[4][4], bf[4][2];
            #pragma unroll
            for (int mt = 0; mt < 4; mt++) {
                const int r = wm * 64 + mt * 16 + g;
                af[mt][0] = Ab[swz_ld(r,     kk)];
                af[mt][1] = Ab[swz_ld(r + 8, kk)];
                af[mt][2] = Ab[swz_ld(r,     kk + 4)];
                af[mt][3] = Ab[swz_ld(r + 8, kk + 4)];
            }
            #pragma unroll
            for (int nt = 0; nt < 4; nt++) {
                const int n = wn * 32 + nt * 8 + g;
                bf[nt][0] = Bb[swz_ld(n, kk)];
                bf[nt][1] = Bb[swz_ld(n, kk + 4)];
            }
            #pragma unroll
            for (int mt = 0; mt < 4; mt++)
                #pragma unroll
                for (int nt = 0; nt < 4; nt++)
                    mma_tf32(acc[mt][nt], af[mt], bf[nt]);
        }

        if (c < 31) {
            uint32_t* An = Asm[nxt];
            #pragma unroll
            for (int i = 0; i < 4; i++) {
                uint4 u;
                u.x = cvt_tf32(ar[i].x); u.y = cvt_tf32(ar[i].y);
                u.z = cvt_tf32(ar[i].z); u.w = cvt_tf32(ar[i].w);
                *(uint4*)&An[swz_st(lrow[i], lkq[i])] = u;
            }
        }
        CP_WAIT0();
        __syncthreads();
    }

    const int gm = m0 + wm * 64;
    const int gn = n0 + wn * 32;
    const int r4 = lane >> 2, c2 = (lane & 3) << 1;
    #pragma unroll
    for (int nt = 0; nt < 4; nt++) {
        const int col = gn + nt * 8 + c2;
        float2 bb = *(const float2*)(bias + col);
        #pragma unroll
        for (int mt = 0; mt < 4; mt++) {
            const int row = gm + mt * 16 + r4;
            float2 lo = {acc[mt][nt][0] + bb.x, acc[mt][nt][1] + bb.y};
            float2 hi = {acc[mt][nt][2] + bb.x, acc[mt][nt][3] + bb.y};
            *(float2*)(C + (size_t)row * D_ + col)       = lo;
            *(float2*)(C + (size_t)(row + 8) * D_ + col) = hi;
        }
    }
}

// ---------------- tensor-core causal flash attention ----------------------
// 64x64 Q tile per CTA, 128 threads (4 warps), warp w owns q rows w*16..+15.
// QK^T and P*V via m16n8k8 tf32. K/V raw fp32 via double-buffered cp.async
// (HW truncates to tf32); Q cvt.rna once. P via 16KB smem tile (warp-private
// rows -> only __syncwarp). One __syncthreads per k-tile.
// Dyn smem words: Qs[0,4096) Ps[4096,8192) K0[8192) V0[12288) K1[16384) V1[20480)
__global__ __launch_bounds__(128, 2)
void flash_mma_kernel(const float* __restrict__ q, const float* __restrict__ k,
                      const float* __restrict__ v, float* __restrict__ o)
{
    extern __shared__ uint32_t fsm[];
    uint32_t* Qs = fsm;
    float*    Pf = (float*)(fsm + 4096);
    const uint32_t sb = smem_u32(fsm);

    const int qt = blockIdx.x, h = blockIdx.y, b = blockIdx.z;
    const int tid = threadIdx.x;
    const int w = tid >> 5, lane = tid & 31;
    const int g = lane >> 2, cc = lane & 3;
    const int qrow = w * 16 + g;

    const size_t base = (size_t)b * S_ * D_ + (size_t)h * DK_;
    const float* qg = q + base + (size_t)qt * 64 * D_;
    const float* kg0 = k + base;
    const float* vg0 = v + base;

    // load Q tile, cvt to tf32, swizzled
    #pragma unroll
    for (int i = 0; i < 8; i++) {
        int id = tid + i * 128;
        int r = id >> 4, c4 = id & 15;
        float4 a4 = *(const float4*)(qg + (size_t)r * D_ + c4 * 4);
        uint4 u;
        u.x = cvt_tf32(a4.x); u.y = cvt_tf32(a4.y);
        u.z = cvt_tf32(a4.z); u.w = cvt_tf32(a4.w);
        *(uint4*)&Qs[swz_st64(r, c4)] = u;
    }

    // prologue: K/V tile 0 into buffer 0
    {
        const uint32_t kB = sb + 8192 * 4, vB = sb + 12288 * 4;
        #pragma unroll
        for (int i = 0; i < 8; i++) {
            int id = tid + i * 128;
            int r = id >> 4, c4 = id & 15;
            cp_async16(kB + swz_st64(r, c4) * 4, kg0 + (size_t)r * D_ + c4 * 4);
            cp_async16(vB + swz_st64(r, c4) * 4, vg0 + (size_t)r * D_ + c4 * 4);
        }
        CP_COMMIT();
    }

    float m0 = -1e30f, m1 = -1e30f, l0 = 0.f, l1 = 0.f;
    float oa[8][4];
    #pragma unroll
    for (int dt = 0; dt < 8; dt++)
        #pragma unroll
        for (int j = 0; j < 4; j++) oa[dt][j] = 0.f;

    for (int kt = 0; kt <= qt; kt++) {
        const int cur = kt & 1;
        CP_WAIT0();
        __syncthreads();

        if (kt < qt) {   // prefetch next K/V into other buffer
            const int nb = cur ^ 1;
            const uint32_t kB = sb + (8192 + nb * 8192) * 4;
            const uint32_t vB = sb + (12288 + nb * 8192) * 4;
            const float* kg = kg0 + (size_t)(kt + 1) * 64 * D_;
            const float* vg = vg0 + (size_t)(kt + 1) * 64 * D_;
            #pragma unroll
            for (int i = 0; i < 8; i++) {
                int id = tid + i * 128;
                int r = id >> 4, c4 = id & 15;
                cp_async16(kB + swz_st64(r, c4) * 4, kg + (size_t)r * D_ + c4 * 4);
                cp_async16(vB + swz_st64(r, c4) * 4, vg + (size_t)r * D_ + c4 * 4);
            }
            CP_COMMIT();
        }

        const uint32_t* Kb = fsm + 8192 + cur * 8192;
        const uint32_t* Vb = fsm + 12288 + cur * 8192;

        // ---- S = Q K^T ----
        float s[8][4];
        #pragma unroll
        for (int t = 0; t < 8; t++)
            #pragma unroll
            for (int j = 0; j < 4; j++) s[t][j] = 0.f;

        #pragma unroll
        for (int ks = 0; ks < 8; ks++) {
            const int kk = ks * 8 + cc;
            uint32_t av[4];
            av[0] = Qs[swz_ld64(qrow,     kk)];
            av[1] = Qs[swz_ld64(qrow + 8, kk)];
            av[2] = Qs[swz_ld64(qrow,     kk + 4)];
            av[3] = Qs[swz_ld64(qrow + 8, kk + 4)];
            #pragma unroll
            for (int t = 0; t < 8; t++) {
                uint32_t bv[2];
                bv[0] = Kb[swz_ld64(t * 8 + g, kk)];
                bv[1] = Kb[swz_ld64(t * 8 + g, kk + 4)];
                mma_tf32(s[t], av, bv);
            }
        }

        // scale + causal mask on diagonal tile
        #pragma unroll
        for (int t = 0; t < 8; t++)
            #pragma unroll
            for (int j = 0; j < 4; j++) s[t][j] *= 0.125f;
        if (kt == qt) {
            #pragma unroll
            for (int t = 0; t < 8; t++) {
                const int n0c = t * 8 + 2 * cc;
                if (n0c     > qrow)     s[t][0] = -1e30f;
                if (n0c + 1 > qrow)     s[t][1] = -1e30f;
                if (n0c     > qrow + 8) s[t][2] = -1e30f;
                if (n0c + 1 > qrow + 8) s[t][3] = -1e30f;
            }
        }

        // ---- online softmax (rows g / g+8, warp-local) ----
        float tm0 = -1e30f, tm1 = -1e30f;
        #pragma unroll
        for (int t = 0; t < 8; t++) {
            tm0 = fmaxf(tm0, fmaxf(s[t][0], s[t][1]));
            tm1 = fmaxf(tm1, fmaxf(s[t][2], s[t][3]));
        }
        #pragma unroll
        for (int off = 1; off <= 2; off <<= 1) {
            tm0 = fmaxf(tm0, __shfl_xor_sync(0xffffffffu, tm0, off));
            tm1 = fmaxf(tm1, __shfl_xor_sync(0xffffffffu, tm1, off));
        }
        const float mn0 = fmaxf(m0, tm0), mn1 = fmaxf(m1, tm1);
        const float corr0 = __expf(m0 - mn0), corr1 = __expf(m1 - mn1);
        m0 = mn0; m1 = mn1;

        float rs0 = 0.f, rs1 = 0.f;
        #pragma unroll
        for (int t = 0; t < 8; t++) {
            const int nc = t * 8 + 2 * cc;
            float p0 = __expf(s[t][0] - m0);
            float p1 = __expf(s[t][1] - m0);
            float p2 = __expf(s[t][2] - m1);
            float p3 = __expf(s[t][3] - m1);
            rs0 += p0 + p1; rs1 += p2 + p3;
            *(float2*)&Pf[swz_ld64(qrow,     nc)] = make_float2(p0, p1);
            *(float2*)&Pf[swz_ld64(qrow + 8, nc)] = make_float2(p2, p3);
        }
        #pragma unroll
        for (int off = 1; off <= 2; off <<= 1) {
            rs0 += __shfl_xor_sync(0xffffffffu, rs0, off);
            rs1 += __shfl_xor_sync(0xffffffffu, rs1, off);
        }
        l0 = l0 * corr0 + rs0;
        l1 = l1 * corr1 + rs1;
        #pragma unroll
        for (int dt = 0; dt < 8; dt++) {
            oa[dt][0] *= corr0; oa[dt][1] *= corr0;
            oa[dt][2] *= corr1; oa[dt][3] *= corr1;
        }
        __syncwarp();

        // ---- O += P V ----
        const uint32_t* Pu = (const uint32_t*)Pf;
        #pragma unroll
        for (int ks = 0; ks < 8; ks++) {
            const int kk = ks * 8 + cc;
            uint32_t pa[4];
            pa[0] = Pu[swz_ld64(qrow,     kk)];
            pa[1] = Pu[swz_ld64(qrow + 8, kk)];
            pa[2] = Pu[swz_ld64(qrow,     kk + 4)];
            pa[3] = Pu[swz_ld64(qrow + 8, kk + 4)];
            #pragma unroll
            for (int dt = 0; dt < 8; dt++) {
                uint32_t bv[2];
                bv[0] = Vb[swz_ld64(kk,     dt * 8 + g)];
                bv[1] = Vb[swz_ld64(kk + 4, dt * 8 + g)];
                mma_tf32(oa[dt], pa, bv);
            }
        }
    }

    // ---- normalize + write ----
    float* og = o + base + (size_t)qt * 64 * D_;
    const float inv0 = 1.f / l0, inv1 = 1.f / l1;
    #pragma unroll
    for (int dt = 0; dt < 8; dt++) {
        const int col = dt * 8 + 2 * cc;
        *(float2*)(og + (size_t)qrow * D_ + col) =
            make_float2(oa[dt][0] * inv0, oa[dt][1] * inv0);
        *(float2*)(og + (size_t)(qrow + 8) * D_ + col) =
            make_float2(oa[dt][2] * inv1, oa[dt][3] * inv1);
    }
}

// ---------------- launch ---------------------------------------------------
extern "C" void kernel_launch(void* const* d_in, const int* in_sizes, int n_in,
                              void* d_out, int out_size)
{
    (void)in_sizes; (void)n_in; (void)out_size;
    const float* Qin  = (const float*)d_in[0];
    const float* KVin = (const float*)d_in[1];
    // d_in[2] = mask (causal by construction; handled analytically)
    const float* Wq = (const float*)d_in[3];
    const float* bq = (const float*)d_in[4];
    const float* Wk = (const float*)d_in[5];
    const float* bk = (const float*)d_in[6];
    const float* Wv = (const float*)d_in[7];
    const float* bv = (const float*)d_in[8];
    const float* Wo = (const float*)d_in[9];
    const float* bo = (const float*)d_in[10];
    float* out = (float*)d_out;

    float *gq, *gk, *gv, *ga, *gwt;
    cudaGetSymbolAddress((void**)&gq,  g_q);
    cudaGetSymbolAddress((void**)&gk,  g_k);
    cudaGetSymbolAddress((void**)&gv,  g_v);
    cudaGetSymbolAddress((void**)&ga,  g_att);
    cudaGetSymbolAddress((void**)&gwt, g_wt);
    float* wt0 = gwt;
    float* wt1 = gwt + (size_t)D_ * D_;
    float* wt2 = gwt + 2 * (size_t)D_ * D_;
    float* wt3 = gwt + 3 * (size_t)D_ * D_;

    static int smem_set = 0;
    if (!smem_set) {
        cudaFuncSetAttribute(gemm_mma_kernel,
                             cudaFuncAttributeMaxDynamicSharedMemorySize, 65536);
        cudaFuncSetAttribute(flash_mma_kernel,
                             cudaFuncAttributeMaxDynamicSharedMemorySize, 98304);
        smem_set = 1;
    }

    dim3 tb(32, 8), tg(32, 32);
    transpose_tf32_kernel<<<tg, tb>>>(Wq, wt0);
    transpose_tf32_kernel<<<tg, tb>>>(Wk, wt1);
    transpose_tf32_kernel<<<tg, tb>>>(Wv, wt2);
    transpose_tf32_kernel<<<tg, tb>>>(Wo, wt3);

    dim3 gg(D_ / 128, M_ / 128);
    gemm_mma_kernel<<<gg, 256, 65536>>>(Qin,  wt0, bq, gq);
    gemm_mma_kernel<<<gg, 256, 65536>>>(KVin, wt1, bk, gk);
    gemm_mma_kernel<<<gg, 256, 65536>>>(KVin, wt2, bv, gv);

    dim3 fg(S_ / 64, H_, B_);
    flash_mma_kernel<<<fg, 128, 98304>>>(gq, gk, gv, ga);

    gemm_mma_kernel<<<gg, 256, 65536>>>(ga, wt3, bo, out);
}